// round 15
// baseline (speedup 1.0000x reference)
#include <cuda_runtime.h>
#include <cuda_fp16.h>
#include <cstdint>

#define BDIM 4096
#define KMOD 4
#define DIN  1024
#define HDIM 1024
#define CTXD 256
#define RHD  64
#define KDIM 4096  /* KMOD*DIN : concatenated reduction dim */

// ---------------- scratch (device globals: no runtime allocation) ----------------
__device__ float   g_c[BDIM * KMOD];                  // gate coeff c[b,k]
__device__ __half  g_A[(size_t)BDIM * KDIM];          // fp16(c*x)   [B][K]
__device__ __half  g_W[(size_t)KDIM * HDIM];          // fp16(W_enc) [K][H]

// ---------------- side stream for router-independent W conversion ----------------
struct SideStream {
    cudaStream_t s2;
    cudaEvent_t  ef, ej;
    SideStream() {
        cudaStreamCreateWithFlags(&s2, cudaStreamNonBlocking);
        cudaEventCreateWithFlags(&ef, cudaEventDisableTiming);
        cudaEventCreateWithFlags(&ej, cudaEventDisableTiming);
    }
};
static SideStream g_ss;

// ---------------- router: smem W1, 2 rows/warp, 8 independent FMA chains (R8) ----------------
#define RROWS 16
__global__ void router_kernel(const float* __restrict__ context,
                              const float* __restrict__ gumbel,
                              const float* __restrict__ W1, const float* __restrict__ b1,
                              const float* __restrict__ gln, const float* __restrict__ bln,
                              const float* __restrict__ W2, const float* __restrict__ b2,
                              const float* __restrict__ W3, const float* __restrict__ b3,
                              const float* __restrict__ prior,
                              const float* __restrict__ fusion_w)
{
    extern __shared__ float rs[];
    float* w1_s  = rs;
    float* w2_s  = w1_s + CTXD * RHD;
    float* w3_s  = w2_s + RHD * (RHD / 2);
    float* ctx_s = w3_s + (RHD / 2) * KMOD;
    float* h1_s  = ctx_s + RROWS * CTXD;
    float* h2_s  = h1_s + RROWS * RHD;

    const int tid = threadIdx.x;
    const int warp = tid >> 5, lane = tid & 31;
    const int b0 = blockIdx.x * RROWS;

    for (int i = tid; i < CTXD * RHD / 4; i += 256)
        reinterpret_cast<float4*>(w1_s)[i] = reinterpret_cast<const float4*>(W1)[i];
    for (int i = tid; i < RHD * (RHD / 2) / 4; i += 256)
        reinterpret_cast<float4*>(w2_s)[i] = reinterpret_cast<const float4*>(W2)[i];
    if (tid < (RHD / 2) * KMOD / 4)
        reinterpret_cast<float4*>(w3_s)[tid] = reinterpret_cast<const float4*>(W3)[tid];
    for (int i = tid; i < RROWS * CTXD / 4; i += 256)
        reinterpret_cast<float4*>(ctx_s)[i] =
            reinterpret_cast<const float4*>(context + (size_t)b0 * CTXD)[i];
    __syncthreads();

    const int r0 = warp * 2, r1 = r0 + 1;
    const float* c0 = ctx_s + r0 * CTXD;
    const float* c1 = ctx_s + r1 * CTXD;

    float acc[2][2][2];
#pragma unroll
    for (int a = 0; a < 2; a++)
#pragma unroll
        for (int b = 0; b < 2; b++)
#pragma unroll
            for (int p = 0; p < 2; p++) acc[a][b][p] = 0.0f;

#pragma unroll 4
    for (int i = 0; i < CTXD; i += 2) {
#pragma unroll
        for (int p = 0; p < 2; p++) {
            const float x0 = c0[i + p];
            const float x1 = c1[i + p];
#pragma unroll
            for (int jj = 0; jj < 2; jj++) {
                const float w = w1_s[(i + p) * RHD + lane + jj * 32];
                acc[0][jj][p] = fmaf(x0, w, acc[0][jj][p]);
                acc[1][jj][p] = fmaf(x1, w, acc[1][jj][p]);
            }
        }
    }

#pragma unroll
    for (int rr = 0; rr < 2; rr++) {
        const int row = (rr == 0) ? r0 : r1;
        float h[2];
#pragma unroll
        for (int jj = 0; jj < 2; jj++)
            h[jj] = acc[rr][jj][0] + acc[rr][jj][1] + b1[lane + jj * 32];

        float s  = h[0] + h[1];
        float sq = h[0] * h[0] + h[1] * h[1];
#pragma unroll
        for (int o = 16; o; o >>= 1) {
            s  += __shfl_xor_sync(0xffffffffu, s,  o);
            sq += __shfl_xor_sync(0xffffffffu, sq, o);
        }
        const float mu   = s * (1.0f / RHD);
        const float var  = sq * (1.0f / RHD) - mu * mu;
        const float rstd = rsqrtf(var + 1e-5f);
#pragma unroll
        for (int jj = 0; jj < 2; jj++) {
            const int j = lane + jj * 32;
            const float v = (h[jj] - mu) * rstd * gln[j] + bln[j];
            h1_s[row * RHD + j] = fmaxf(v, 0.0f);
        }
        __syncwarp();
        float a2a = 0.0f, a2b = 0.0f;
#pragma unroll 4
        for (int i = 0; i < RHD; i += 2) {
            a2a = fmaf(h1_s[row * RHD + i],     w2_s[i * (RHD / 2) + lane],       a2a);
            a2b = fmaf(h1_s[row * RHD + i + 1], w2_s[(i + 1) * (RHD / 2) + lane], a2b);
        }
        h2_s[row * (RHD / 2) + lane] = fmaxf(a2a + a2b + b2[lane], 0.0f);
        __syncwarp();

        float logit = 0.0f;
        if (lane < KMOD) {
            logit = b3[lane] + prior[lane];
            for (int i = 0; i < RHD / 2; i++)
                logit = fmaf(h2_s[row * (RHD / 2) + i], w3_s[i * KMOD + lane], logit);
        }
        float lg[4];
#pragma unroll
        for (int k = 0; k < 4; k++) lg[k] = __shfl_sync(0xffffffffu, logit, k);

        if (lane == 0) {
            const int b = b0 + row;
            float fw[4], m = -1e30f;
#pragma unroll
            for (int k = 0; k < 4; k++) { fw[k] = fusion_w[k]; m = fmaxf(m, fw[k]); }
            float se = 0.0f;
#pragma unroll
            for (int k = 0; k < 4; k++) { fw[k] = expf(fw[k] - m); se += fw[k]; }
            const float inv = 1.0f / se;
            int i1 = 0;
#pragma unroll
            for (int k = 1; k < 4; k++) if (lg[k] > lg[i1]) i1 = k;
            int i2 = (i1 == 0) ? 1 : 0;
#pragma unroll
            for (int k = 0; k < 4; k++) if (k != i1 && lg[k] > lg[i2]) i2 = k;
#pragma unroll
            for (int k = 0; k < 4; k++) {
                const float soft = 1.0f / (1.0f + expf(-(lg[k] + gumbel[b * KMOD + k])));
                const float mask = (k == i1 || k == i2) ? fmaxf(soft, 1.0f) : soft;
                const float cc   = (mask > 0.5f) ? (fw[k] * inv) * mask : 0.0f;
                g_c[b * KMOD + k] = cc;
            }
        }
    }
}
#define ROUTER_SMEM ((CTXD * RHD + RHD * (RHD / 2) + (RHD / 2) * KMOD \
                      + RROWS * CTXD + RROWS * RHD + RROWS * (RHD / 2)) * 4)

// ---------------- W_enc -> g_W fp16 (side stream; router-independent) ----------------
#define W4 (KDIM * HDIM / 4)          /* 1048576 float4 units */
__global__ void convw_kernel(const float* __restrict__ W_enc)
{
    const int stride = gridDim.x * blockDim.x;
    for (int t = blockIdx.x * blockDim.x + threadIdx.x; t < W4; t += stride) {
        const float4 v = reinterpret_cast<const float4*>(W_enc)[t];
        __half2 p0 = __halves2half2(__float2half_rn(v.x), __float2half_rn(v.y));
        __half2 p1 = __halves2half2(__float2half_rn(v.z), __float2half_rn(v.w));
        uint2 o;
        o.x = *reinterpret_cast<uint32_t*>(&p0);
        o.y = *reinterpret_cast<uint32_t*>(&p1);
        reinterpret_cast<uint2*>(g_W)[t] = o;
    }
}

// ---------------- gated fp16 convert of x: g_A[b, k*DIN+d] = c[b,k]*x[k,b,d] ----------------
#define A4 (KMOD * BDIM * (DIN / 4))  /* 4194304 float4 units */
__global__ void conva_kernel(const float* __restrict__ x)
{
    const int stride = gridDim.x * blockDim.x;
    for (int t = blockIdx.x * blockDim.x + threadIdx.x; t < A4; t += stride) {
        const int d4  = t & (DIN / 4 - 1);
        const int rem = t >> 8;
        const int b   = rem & (BDIM - 1);
        const int mod = rem >> 12;
        const float cc = g_c[b * KMOD + mod];
        const float4 v = reinterpret_cast<const float4*>(x)[t];
        __half2 p0 = __halves2half2(__float2half_rn(v.x * cc), __float2half_rn(v.y * cc));
        __half2 p1 = __halves2half2(__float2half_rn(v.z * cc), __float2half_rn(v.w * cc));
        uint2 o;
        o.x = *reinterpret_cast<uint32_t*>(&p0);
        o.y = *reinterpret_cast<uint32_t*>(&p1);
        const size_t aidx4 = ((size_t)b * KDIM + (size_t)mod * DIN) / 4 + d4;
        reinterpret_cast<uint2*>(g_A)[aidx4] = o;
    }
}

// ---------------- main GEMM: 64x64 warp tiles, occ 1, 4-stage ring ----------------
#define BM 128
#define BN 256
#define BK 64
#define KT (KDIM / BK)                /* 64 iterations */
#define NSTAGE 4
#define ASTR 72                       /* fp16 units; 144B row stride -> conflict-free */
#define BSTR 264                      /* fp16 units; 528B row stride */
#define A_BYTES (BM * ASTR * 2)       /* 18432 */
#define B_BYTES (BK * BSTR * 2)       /* 33792 */
#define OFF_B   A_BYTES
#define STAGE_BYTES (A_BYTES + B_BYTES)  /* 52224 */

__device__ __forceinline__ void cp16(uint32_t dst, const void* src)
{
    asm volatile("cp.async.cg.shared.global [%0], [%1], 16;\n" :: "r"(dst), "l"(src));
}
__device__ __forceinline__ void ldsm4(uint32_t* r, uint32_t addr)
{
    asm volatile("ldmatrix.sync.aligned.m8n8.x4.shared.b16 {%0,%1,%2,%3}, [%4];\n"
                 : "=r"(r[0]), "=r"(r[1]), "=r"(r[2]), "=r"(r[3]) : "r"(addr));
}
__device__ __forceinline__ void ldsm4t(uint32_t* r, uint32_t addr)
{
    asm volatile("ldmatrix.sync.aligned.m8n8.x4.trans.shared.b16 {%0,%1,%2,%3}, [%4];\n"
                 : "=r"(r[0]), "=r"(r[1]), "=r"(r[2]), "=r"(r[3]) : "r"(addr));
}
__device__ __forceinline__ void mma16816(float* d, const uint32_t* a, const uint32_t* b)
{
    asm volatile("mma.sync.aligned.m16n8k16.row.col.f32.f16.f16.f32 "
                 "{%0,%1,%2,%3},{%4,%5,%6,%7},{%8,%9},{%0,%1,%2,%3};\n"
                 : "+f"(d[0]), "+f"(d[1]), "+f"(d[2]), "+f"(d[3])
                 : "r"(a[0]), "r"(a[1]), "r"(a[2]), "r"(a[3]), "r"(b[0]), "r"(b[1]));
}

__global__ void __launch_bounds__(256, 1)
gemm_kernel(float* __restrict__ out, const float* __restrict__ b_enc)
{
    extern __shared__ char smem[];
    const int tid = threadIdx.x;
    const int warp = tid >> 5, lane = tid & 31;
    const int n0 = blockIdx.x * BN;
    const int m0 = blockIdx.y * BM;
    const int wm = warp & 1, wn = warp >> 1;   // 2 (M) x 4 (N) warps; warp tile 64x64

    const uint32_t sbase = (uint32_t)__cvta_generic_to_shared(smem);

    float d[4][8][4];
#pragma unroll
    for (int mt = 0; mt < 4; mt++)
#pragma unroll
        for (int nt = 0; nt < 8; nt++)
#pragma unroll
            for (int i = 0; i < 4; i++) d[mt][nt][i] = 0.0f;

    auto loadSlice = [&](uint32_t st, int bk, int g) {
        if (g < 4) {
            const int idx = g * 256 + tid;
            const int r = idx >> 3, c = idx & 7;
            cp16(st + (uint32_t)(r * ASTR + c * 8) * 2,
                 g_A + (size_t)(m0 + r) * KDIM + bk + c * 8);
        } else {
            const int idx = (g - 4) * 256 + tid;
            const int r = idx >> 5, c = idx & 31;
            cp16(st + OFF_B + (uint32_t)(r * BSTR + c * 8) * 2,
                 g_W + (size_t)(bk + r) * HDIM + n0 + c * 8);
        }
    };
    auto loadStage = [&](int s, int kt) {
        const uint32_t st = sbase + (uint32_t)s * STAGE_BYTES;
#pragma unroll
        for (int g = 0; g < 12; g++) loadSlice(st, kt * BK, g);
        asm volatile("cp.async.commit_group;\n");
    };

    uint32_t af[2][4][4], bf[2][4][4];
    auto loadFrags = [&](uint32_t st, int ks, int buf) {
#pragma unroll
        for (int mt = 0; mt < 4; mt++) {
            const int r = wm * 64 + mt * 16 + (lane & 15);
            const int c = ks * 16 + (lane >> 4) * 8;
            ldsm4(af[buf][mt], st + (uint32_t)(r * ASTR + c) * 2);
        }
        const int part = lane >> 3;
        const int kr = ks * 16 + (part & 1) * 8 + (lane & 7);
#pragma unroll
        for (int g = 0; g < 4; g++) {
            const int ncol = wn * 64 + g * 16 + (part >> 1) * 8;
            ldsm4t(bf[buf][g], st + OFF_B + (uint32_t)(kr * BSTR + ncol) * 2);
        }
    };

    loadStage(0, 0);
    loadStage(1, 1);
    loadStage(2, 2);

    for (int kt = 0; kt < KT; kt++) {
        if      (kt < KT - 2) asm volatile("cp.async.wait_group 2;\n");
        else if (kt < KT - 1) asm volatile("cp.async.wait_group 1;\n");
        else                  asm volatile("cp.async.wait_group 0;\n");
        __syncthreads();

        const uint32_t st = sbase + (uint32_t)(kt & (NSTAGE - 1)) * STAGE_BYTES;
        loadFrags(st, 0, 0);

        const bool pf = (kt + 3 < KT);
        const uint32_t pst = sbase + (uint32_t)((kt + 3) & (NSTAGE - 1)) * STAGE_BYTES;
        const int pbk = (kt + 3) * BK;

#pragma unroll
        for (int ks = 0; ks < 4; ks++) {
            if (ks < 3) loadFrags(st, ks + 1, (ks + 1) & 1);
            if (pf) {               // spread prefetch: 3 chunk-groups per ks
                loadSlice(pst, pbk, 3 * ks + 0);
                loadSlice(pst, pbk, 3 * ks + 1);
                loadSlice(pst, pbk, 3 * ks + 2);
            }
            const int cur = ks & 1;
#pragma unroll
            for (int mt = 0; mt < 4; mt++)
#pragma unroll
                for (int g = 0; g < 4; g++)
#pragma unroll
                    for (int h = 0; h < 2; h++)
                        mma16816(d[mt][g * 2 + h], af[cur][mt], &bf[cur][g][h * 2]);
        }
        if (pf) asm volatile("cp.async.commit_group;\n");
    }

    // epilogue: + sum_k c[b,k]*b_enc[k,h]
#pragma unroll
    for (int mt = 0; mt < 4; mt++) {
        const int rbase = m0 + wm * 64 + mt * 16 + (lane >> 2);
#pragma unroll
        for (int half = 0; half < 2; half++) {
            const int r = rbase + half * 8;
            const float4 c4 = *reinterpret_cast<const float4*>(&g_c[r * KMOD]);
#pragma unroll
            for (int nt = 0; nt < 8; nt++) {
                const int c = n0 + wn * 64 + nt * 8 + (lane & 3) * 2;
                const float bias0 = c4.x * b_enc[0 * HDIM + c]     + c4.y * b_enc[1 * HDIM + c]
                                  + c4.z * b_enc[2 * HDIM + c]     + c4.w * b_enc[3 * HDIM + c];
                const float bias1 = c4.x * b_enc[0 * HDIM + c + 1] + c4.y * b_enc[1 * HDIM + c + 1]
                                  + c4.z * b_enc[2 * HDIM + c + 1] + c4.w * b_enc[3 * HDIM + c + 1];
                float2 o;
                o.x = d[mt][nt][half * 2 + 0] + bias0;
                o.y = d[mt][nt][half * 2 + 1] + bias1;
                *reinterpret_cast<float2*>(out + (size_t)r * HDIM + c) = o;
            }
        }
    }
}

// ---------------- launch ----------------
extern "C" void kernel_launch(void* const* d_in, const int* in_sizes, int n_in,
                              void* d_out, int out_size)
{
    const float* context  = (const float*)d_in[0];
    const float* x        = (const float*)d_in[1];
    const float* gumbel   = (const float*)d_in[2];
    const float* W1       = (const float*)d_in[3];
    const float* b1       = (const float*)d_in[4];
    const float* gln      = (const float*)d_in[5];
    const float* bln      = (const float*)d_in[6];
    const float* W2       = (const float*)d_in[7];
    const float* b2       = (const float*)d_in[8];
    const float* W3       = (const float*)d_in[9];
    const float* b3       = (const float*)d_in[10];
    const float* prior    = (const float*)d_in[11];
    const float* W_enc    = (const float*)d_in[12];
    const float* b_enc    = (const float*)d_in[13];
    const float* fusion_w = (const float*)d_in[14];
    float* out = (float*)d_out;

    // fork: convW runs on the side stream concurrently with the router
    cudaEventRecord(g_ss.ef, (cudaStream_t)0);
    cudaStreamWaitEvent(g_ss.s2, g_ss.ef, 0);
    convw_kernel<<<1184, 256, 0, g_ss.s2>>>(W_enc);
    cudaEventRecord(g_ss.ej, g_ss.s2);

    cudaFuncSetAttribute(router_kernel, cudaFuncAttributeMaxDynamicSharedMemorySize,
                         ROUTER_SMEM);
    router_kernel<<<BDIM / RROWS, 256, ROUTER_SMEM>>>(context, gumbel, W1, b1, gln, bln,
                                                      W2, b2, W3, b3, prior, fusion_w);
    conva_kernel<<<2368, 256>>>(x);

    // join: GEMM needs g_W from the side stream
    cudaStreamWaitEvent((cudaStream_t)0, g_ss.ej, 0);

    const int dyn = NSTAGE * STAGE_BYTES;   // 208896
    cudaFuncSetAttribute(gemm_kernel, cudaFuncAttributeMaxDynamicSharedMemorySize, dyn);
    gemm_kernel<<<dim3(HDIM / BN, BDIM / BM), 256, dyn>>>(out, b_enc);
}

// round 16
// speedup vs baseline: 1.0869x; 1.0869x over previous
#include <cuda_runtime.h>
#include <cuda_fp16.h>
#include <cstdint>

#define BDIM 4096
#define KMOD 4
#define DIN  1024
#define HDIM 1024
#define CTXD 256
#define RHD  64
#define KDIM 4096  /* KMOD*DIN : concatenated reduction dim */

// ---------------- scratch (device globals: no runtime allocation) ----------------
__device__ float   g_c[BDIM * KMOD];                  // gate coeff c[b,k]
__device__ __half  g_A[(size_t)BDIM * KDIM];          // fp16(c*x)   [B][K]
__device__ __half  g_W[(size_t)KDIM * HDIM];          // fp16(W_enc) [K][H]

// ---------------- router: smem W1, 2 rows/warp, 8 independent FMA chains (R8) ----------------
#define RROWS 16
__global__ void router_kernel(const float* __restrict__ context,
                              const float* __restrict__ gumbel,
                              const float* __restrict__ W1, const float* __restrict__ b1,
                              const float* __restrict__ gln, const float* __restrict__ bln,
                              const float* __restrict__ W2, const float* __restrict__ b2,
                              const float* __restrict__ W3, const float* __restrict__ b3,
                              const float* __restrict__ prior,
                              const float* __restrict__ fusion_w)
{
    extern __shared__ float rs[];
    float* w1_s  = rs;
    float* w2_s  = w1_s + CTXD * RHD;
    float* w3_s  = w2_s + RHD * (RHD / 2);
    float* ctx_s = w3_s + (RHD / 2) * KMOD;
    float* h1_s  = ctx_s + RROWS * CTXD;
    float* h2_s  = h1_s + RROWS * RHD;

    const int tid = threadIdx.x;
    const int warp = tid >> 5, lane = tid & 31;
    const int b0 = blockIdx.x * RROWS;

    for (int i = tid; i < CTXD * RHD / 4; i += 256)
        reinterpret_cast<float4*>(w1_s)[i] = reinterpret_cast<const float4*>(W1)[i];
    for (int i = tid; i < RHD * (RHD / 2) / 4; i += 256)
        reinterpret_cast<float4*>(w2_s)[i] = reinterpret_cast<const float4*>(W2)[i];
    if (tid < (RHD / 2) * KMOD / 4)
        reinterpret_cast<float4*>(w3_s)[tid] = reinterpret_cast<const float4*>(W3)[tid];
    for (int i = tid; i < RROWS * CTXD / 4; i += 256)
        reinterpret_cast<float4*>(ctx_s)[i] =
            reinterpret_cast<const float4*>(context + (size_t)b0 * CTXD)[i];
    __syncthreads();

    const int r0 = warp * 2, r1 = r0 + 1;
    const float* c0 = ctx_s + r0 * CTXD;
    const float* c1 = ctx_s + r1 * CTXD;

    float acc[2][2][2];
#pragma unroll
    for (int a = 0; a < 2; a++)
#pragma unroll
        for (int b = 0; b < 2; b++)
#pragma unroll
            for (int p = 0; p < 2; p++) acc[a][b][p] = 0.0f;

#pragma unroll 4
    for (int i = 0; i < CTXD; i += 2) {
#pragma unroll
        for (int p = 0; p < 2; p++) {
            const float x0 = c0[i + p];
            const float x1 = c1[i + p];
#pragma unroll
            for (int jj = 0; jj < 2; jj++) {
                const float w = w1_s[(i + p) * RHD + lane + jj * 32];
                acc[0][jj][p] = fmaf(x0, w, acc[0][jj][p]);
                acc[1][jj][p] = fmaf(x1, w, acc[1][jj][p]);
            }
        }
    }

#pragma unroll
    for (int rr = 0; rr < 2; rr++) {
        const int row = (rr == 0) ? r0 : r1;
        float h[2];
#pragma unroll
        for (int jj = 0; jj < 2; jj++)
            h[jj] = acc[rr][jj][0] + acc[rr][jj][1] + b1[lane + jj * 32];

        float s  = h[0] + h[1];
        float sq = h[0] * h[0] + h[1] * h[1];
#pragma unroll
        for (int o = 16; o; o >>= 1) {
            s  += __shfl_xor_sync(0xffffffffu, s,  o);
            sq += __shfl_xor_sync(0xffffffffu, sq, o);
        }
        const float mu   = s * (1.0f / RHD);
        const float var  = sq * (1.0f / RHD) - mu * mu;
        const float rstd = rsqrtf(var + 1e-5f);
#pragma unroll
        for (int jj = 0; jj < 2; jj++) {
            const int j = lane + jj * 32;
            const float v = (h[jj] - mu) * rstd * gln[j] + bln[j];
            h1_s[row * RHD + j] = fmaxf(v, 0.0f);
        }
        __syncwarp();
        float a2a = 0.0f, a2b = 0.0f;
#pragma unroll 4
        for (int i = 0; i < RHD; i += 2) {
            a2a = fmaf(h1_s[row * RHD + i],     w2_s[i * (RHD / 2) + lane],       a2a);
            a2b = fmaf(h1_s[row * RHD + i + 1], w2_s[(i + 1) * (RHD / 2) + lane], a2b);
        }
        h2_s[row * (RHD / 2) + lane] = fmaxf(a2a + a2b + b2[lane], 0.0f);
        __syncwarp();

        float logit = 0.0f;
        if (lane < KMOD) {
            logit = b3[lane] + prior[lane];
            for (int i = 0; i < RHD / 2; i++)
                logit = fmaf(h2_s[row * (RHD / 2) + i], w3_s[i * KMOD + lane], logit);
        }
        float lg[4];
#pragma unroll
        for (int k = 0; k < 4; k++) lg[k] = __shfl_sync(0xffffffffu, logit, k);

        if (lane == 0) {
            const int b = b0 + row;
            float fw[4], m = -1e30f;
#pragma unroll
            for (int k = 0; k < 4; k++) { fw[k] = fusion_w[k]; m = fmaxf(m, fw[k]); }
            float se = 0.0f;
#pragma unroll
            for (int k = 0; k < 4; k++) { fw[k] = expf(fw[k] - m); se += fw[k]; }
            const float inv = 1.0f / se;
            int i1 = 0;
#pragma unroll
            for (int k = 1; k < 4; k++) if (lg[k] > lg[i1]) i1 = k;
            int i2 = (i1 == 0) ? 1 : 0;
#pragma unroll
            for (int k = 0; k < 4; k++) if (k != i1 && lg[k] > lg[i2]) i2 = k;
#pragma unroll
            for (int k = 0; k < 4; k++) {
                const float soft = 1.0f / (1.0f + expf(-(lg[k] + gumbel[b * KMOD + k])));
                const float mask = (k == i1 || k == i2) ? fmaxf(soft, 1.0f) : soft;
                const float cc   = (mask > 0.5f) ? (fw[k] * inv) * mask : 0.0f;
                g_c[b * KMOD + k] = cc;
            }
        }
    }
}
#define ROUTER_SMEM ((CTXD * RHD + RHD * (RHD / 2) + (RHD / 2) * KMOD \
                      + RROWS * CTXD + RROWS * RHD + RROWS * (RHD / 2)) * 4)

// ---------------- combined fp16 conversion: W_enc -> g_W, c*x -> g_A ----------------
#define W4 (KDIM * HDIM / 4)          /* 1048576 float4 units */
#define A4 (KMOD * BDIM * (DIN / 4))  /* 4194304 float4 units */
__global__ void conv_kernel(const float* __restrict__ x, const float* __restrict__ W_enc)
{
    const int stride = gridDim.x * blockDim.x;
    for (int t = blockIdx.x * blockDim.x + threadIdx.x; t < W4 + A4; t += stride) {
        if (t < W4) {
            const float4 v = reinterpret_cast<const float4*>(W_enc)[t];
            __half2 p0 = __halves2half2(__float2half_rn(v.x), __float2half_rn(v.y));
            __half2 p1 = __halves2half2(__float2half_rn(v.z), __float2half_rn(v.w));
            uint2 o;
            o.x = *reinterpret_cast<uint32_t*>(&p0);
            o.y = *reinterpret_cast<uint32_t*>(&p1);
            reinterpret_cast<uint2*>(g_W)[t] = o;
        } else {
            const int ta = t - W4;
            const int d4  = ta & (DIN / 4 - 1);
            const int rem = ta >> 8;
            const int b   = rem & (BDIM - 1);
            const int mod = rem >> 12;
            const float cc = g_c[b * KMOD + mod];
            const float4 v = reinterpret_cast<const float4*>(x)[ta];
            __half2 p0 = __halves2half2(__float2half_rn(v.x * cc), __float2half_rn(v.y * cc));
            __half2 p1 = __halves2half2(__float2half_rn(v.z * cc), __float2half_rn(v.w * cc));
            uint2 o;
            o.x = *reinterpret_cast<uint32_t*>(&p0);
            o.y = *reinterpret_cast<uint32_t*>(&p1);
            const size_t aidx4 = ((size_t)b * KDIM + (size_t)mod * DIN) / 4 + d4;
            reinterpret_cast<uint2*>(g_A)[aidx4] = o;
        }
    }
}

// ---------------- main GEMM: 64x64 warp tiles, cross-kt fragment pipelining ----------------
#define BM 128
#define BN 256
#define BK 64
#define KT (KDIM / BK)                /* 64 iterations */
#define NSTAGE 4
#define ASTR 72                       /* fp16 units; 144B row stride -> conflict-free */
#define BSTR 264                      /* fp16 units; 528B row stride */
#define A_BYTES (BM * ASTR * 2)       /* 18432 */
#define B_BYTES (BK * BSTR * 2)       /* 33792 */
#define OFF_B   A_BYTES
#define STAGE_BYTES (A_BYTES + B_BYTES)  /* 52224 */

__device__ __forceinline__ void cp16(uint32_t dst, const void* src)
{
    asm volatile("cp.async.cg.shared.global [%0], [%1], 16;\n" :: "r"(dst), "l"(src));
}
__device__ __forceinline__ void ldsm4(uint32_t* r, uint32_t addr)
{
    asm volatile("ldmatrix.sync.aligned.m8n8.x4.shared.b16 {%0,%1,%2,%3}, [%4];\n"
                 : "=r"(r[0]), "=r"(r[1]), "=r"(r[2]), "=r"(r[3]) : "r"(addr));
}
__device__ __forceinline__ void ldsm4t(uint32_t* r, uint32_t addr)
{
    asm volatile("ldmatrix.sync.aligned.m8n8.x4.trans.shared.b16 {%0,%1,%2,%3}, [%4];\n"
                 : "=r"(r[0]), "=r"(r[1]), "=r"(r[2]), "=r"(r[3]) : "r"(addr));
}
__device__ __forceinline__ void mma16816(float* d, const uint32_t* a, const uint32_t* b)
{
    asm volatile("mma.sync.aligned.m16n8k16.row.col.f32.f16.f16.f32 "
                 "{%0,%1,%2,%3},{%4,%5,%6,%7},{%8,%9},{%0,%1,%2,%3};\n"
                 : "+f"(d[0]), "+f"(d[1]), "+f"(d[2]), "+f"(d[3])
                 : "r"(a[0]), "r"(a[1]), "r"(a[2]), "r"(a[3]), "r"(b[0]), "r"(b[1]));
}

__global__ void __launch_bounds__(256, 1)
gemm_kernel(float* __restrict__ out, const float* __restrict__ b_enc)
{
    extern __shared__ char smem[];
    const int tid = threadIdx.x;
    const int warp = tid >> 5, lane = tid & 31;
    const int n0 = blockIdx.x * BN;
    const int m0 = blockIdx.y * BM;
    const int wm = warp & 1, wn = warp >> 1;   // 2 (M) x 4 (N) warps; warp tile 64x64

    const uint32_t sbase = (uint32_t)__cvta_generic_to_shared(smem);

    float d[4][8][4];
#pragma unroll
    for (int mt = 0; mt < 4; mt++)
#pragma unroll
        for (int nt = 0; nt < 8; nt++)
#pragma unroll
            for (int i = 0; i < 4; i++) d[mt][nt][i] = 0.0f;

    auto loadSlice = [&](uint32_t st, int bk, int g) {
        if (g < 4) {
            const int idx = g * 256 + tid;
            const int r = idx >> 3, c = idx & 7;
            cp16(st + (uint32_t)(r * ASTR + c * 8) * 2,
                 g_A + (size_t)(m0 + r) * KDIM + bk + c * 8);
        } else {
            const int idx = (g - 4) * 256 + tid;
            const int r = idx >> 5, c = idx & 31;
            cp16(st + OFF_B + (uint32_t)(r * BSTR + c * 8) * 2,
                 g_W + (size_t)(bk + r) * HDIM + n0 + c * 8);
        }
    };
    auto loadStage = [&](int s, int kt) {
        const uint32_t st = sbase + (uint32_t)s * STAGE_BYTES;
#pragma unroll
        for (int g = 0; g < 12; g++) loadSlice(st, kt * BK, g);
        asm volatile("cp.async.commit_group;\n");
    };

    uint32_t af[2][4][4], bf[2][4][4];
    auto loadFrags = [&](uint32_t st, int ks, int buf) {
#pragma unroll
        for (int mt = 0; mt < 4; mt++) {
            const int r = wm * 64 + mt * 16 + (lane & 15);
            const int c = ks * 16 + (lane >> 4) * 8;
            ldsm4(af[buf][mt], st + (uint32_t)(r * ASTR + c) * 2);
        }
        const int part = lane >> 3;
        const int kr = ks * 16 + (part & 1) * 8 + (lane & 7);
#pragma unroll
        for (int g = 0; g < 4; g++) {
            const int ncol = wn * 64 + g * 16 + (part >> 1) * 8;
            ldsm4t(bf[buf][g], st + OFF_B + (uint32_t)(kr * BSTR + ncol) * 2);
        }
    };

    loadStage(0, 0);
    loadStage(1, 1);
    loadStage(2, 2);
    asm volatile("cp.async.wait_group 1;\n");   // stages 0,1 complete (own thread)
    __syncthreads();                             // ... all threads
    loadFrags(sbase, 0, 0);                      // frags (kt=0, ks=0)

    for (int kt = 0; kt < KT; kt++) {
        const uint32_t st  = sbase + (uint32_t)(kt & (NSTAGE - 1)) * STAGE_BYTES;
        const uint32_t nst = sbase + (uint32_t)((kt + 1) & (NSTAGE - 1)) * STAGE_BYTES;
        const bool pf = (kt + 3 < KT);
        const uint32_t pst = sbase + (uint32_t)((kt + 3) & (NSTAGE - 1)) * STAGE_BYTES;
        const int pbk = (kt + 3) * BK;

#pragma unroll
        for (int ks = 0; ks < 4; ks++) {
            if (ks < 3)               loadFrags(st, ks + 1, (ks + 1) & 1);
            else if (kt + 1 < KT)     loadFrags(nst, 0, 0);     // cross-kt prefetch
            if (pf) {               // spread prefetch: 3 chunk-groups per ks
                loadSlice(pst, pbk, 3 * ks + 0);
                loadSlice(pst, pbk, 3 * ks + 1);
                loadSlice(pst, pbk, 3 * ks + 2);
            }
            const int cur = ks & 1;
#pragma unroll
            for (int mt = 0; mt < 4; mt++)
#pragma unroll
                for (int g = 0; g < 4; g++)
#pragma unroll
                    for (int h = 0; h < 2; h++)
                        mma16816(d[mt][g * 2 + h], af[cur][mt], &bf[cur][g][h * 2]);
        }
        if (pf) asm volatile("cp.async.commit_group;\n");

        if (kt + 1 < KT) {
            if (kt + 3 < KT) asm volatile("cp.async.wait_group 1;\n");
            else             asm volatile("cp.async.wait_group 0;\n");
            __syncthreads();
        }
    }

    // epilogue: + sum_k c[b,k]*b_enc[k,h]
#pragma unroll
    for (int mt = 0; mt < 4; mt++) {
        const int rbase = m0 + wm * 64 + mt * 16 + (lane >> 2);
#pragma unroll
        for (int half = 0; half < 2; half++) {
            const int r = rbase + half * 8;
            const float4 c4 = *reinterpret_cast<const float4*>(&g_c[r * KMOD]);
#pragma unroll
            for (int nt = 0; nt < 8; nt++) {
                const int c = n0 + wn * 64 + nt * 8 + (lane & 3) * 2;
                const float bias0 = c4.x * b_enc[0 * HDIM + c]     + c4.y * b_enc[1 * HDIM + c]
                                  + c4.z * b_enc[2 * HDIM + c]     + c4.w * b_enc[3 * HDIM + c];
                const float bias1 = c4.x * b_enc[0 * HDIM + c + 1] + c4.y * b_enc[1 * HDIM + c + 1]
                                  + c4.z * b_enc[2 * HDIM + c + 1] + c4.w * b_enc[3 * HDIM + c + 1];
                float2 o;
                o.x = d[mt][nt][half * 2 + 0] + bias0;
                o.y = d[mt][nt][half * 2 + 1] + bias1;
                *reinterpret_cast<float2*>(out + (size_t)r * HDIM + c) = o;
            }
        }
    }
}

// ---------------- launch ----------------
extern "C" void kernel_launch(void* const* d_in, const int* in_sizes, int n_in,
                              void* d_out, int out_size)
{
    const float* context  = (const float*)d_in[0];
    const float* x        = (const float*)d_in[1];
    const float* gumbel   = (const float*)d_in[2];
    const float* W1       = (const float*)d_in[3];
    const float* b1       = (const float*)d_in[4];
    const float* gln      = (const float*)d_in[5];
    const float* bln      = (const float*)d_in[6];
    const float* W2       = (const float*)d_in[7];
    const float* b2       = (const float*)d_in[8];
    const float* W3       = (const float*)d_in[9];
    const float* b3       = (const float*)d_in[10];
    const float* prior    = (const float*)d_in[11];
    const float* W_enc    = (const float*)d_in[12];
    const float* b_enc    = (const float*)d_in[13];
    const float* fusion_w = (const float*)d_in[14];
    float* out = (float*)d_out;

    cudaFuncSetAttribute(router_kernel, cudaFuncAttributeMaxDynamicSharedMemorySize,
                         ROUTER_SMEM);
    router_kernel<<<BDIM / RROWS, 256, ROUTER_SMEM>>>(context, gumbel, W1, b1, gln, bln,
                                                      W2, b2, W3, b3, prior, fusion_w);
    conv_kernel<<<2368, 256>>>(x, W_enc);   // 16 blocks x 148 SMs

    const int dyn = NSTAGE * STAGE_BYTES;   // 208896
    cudaFuncSetAttribute(gemm_kernel, cudaFuncAttributeMaxDynamicSharedMemorySize, dyn);
    gemm_kernel<<<dim3(HDIM / BN, BDIM / BM), 256, dyn>>>(out, b_enc);
}